// round 16
// baseline (speedup 1.0000x reference)
#include <cuda_runtime.h>
#include <cuda_fp16.h>
#include <cuda_bf16.h>
#include <math.h>

#define N_NODES 100000
#define E_MAX   1600000
#define ET_MAX  (E_MAX + N_NODES)
#define HID     64
#define IN_DIM  128
#define NCLS    40
#define CAP     64                     // bucket capacity per node (P(overflow)~1e-19)

// ---------------- scratch (device globals; no allocation allowed) ----------
__device__ __half g_h[(size_t)N_NODES * HID];   // transformed features (fp16)
__device__ float  g_acc[(size_t)N_NODES * HID]; // layer output / next input
__device__ float  g_s[N_NODES];
__device__ float  g_d[N_NODES];
__device__ int    g_deg[N_NODES];
__device__ int    g_csr[(size_t)N_NODES * CAP]; // bucketed src lists
__device__ int    g_is64;
// pre-converted weights: interleaved {hi,lo} bf16x2 packs of (k,k+1), k2-major
__device__ uint2  g_w0pk[(IN_DIM / 2) * 64];
__device__ uint2  g_w1pk[(HID / 2) * 64];

// ---------------- helpers ----------------------------------------------------
__device__ __forceinline__ unsigned u32bf2(__nv_bfloat162 h) {
    return *reinterpret_cast<unsigned*>(&h);
}
__device__ __forceinline__ void mma16816(float* c, const unsigned* a,
                                         const unsigned* b) {
    asm volatile(
        "mma.sync.aligned.m16n8k16.row.col.f32.bf16.bf16.f32 "
        "{%0,%1,%2,%3}, {%4,%5,%6,%7}, {%8,%9}, {%0,%1,%2,%3};"
        : "+f"(c[0]), "+f"(c[1]), "+f"(c[2]), "+f"(c[3])
        : "r"(a[0]), "r"(a[1]), "r"(a[2]), "r"(a[3]), "r"(b[0]), "r"(b[1]));
}

__device__ __forceinline__ void load_edge(const void* ei, int i, int E,
                                          int& src, int& dst) {
    if (i >= E) { int v = i - E; src = v; dst = v; return; }   // self-loop
    if (g_is64) {
        const long long* p = (const long long*)ei;
        src = (int)p[i];
        dst = (int)p[(long long)E + i];
    } else {
        const int* p = (const int*)ei;
        src = p[i];
        dst = p[E + i];
    }
}

// ---------------- weight pre-conversion (once, ~2us) -------------------------
__global__ void wconv_kernel(const float* __restrict__ W0,
                             const float* __restrict__ W1) {
    int i = blockIdx.x * blockDim.x + threadIdx.x;
    const int NW0 = (IN_DIM / 2) * 64;
    const int NW1 = (HID / 2) * 64;
    if (i < NW0) {
        int k2 = i >> 6, c = i & 63;
        float x = W0[(2 * k2) * 64 + c], y = W0[(2 * k2 + 1) * 64 + c];
        __nv_bfloat162 hh = __floats2bfloat162_rn(x, y);
        float2 hf = __bfloat1622float2(hh);
        __nv_bfloat162 ll = __floats2bfloat162_rn(x - hf.x, y - hf.y);
        g_w0pk[i] = make_uint2(u32bf2(hh), u32bf2(ll));
    } else if (i < NW0 + NW1) {
        int j = i - NW0;
        int k2 = j >> 6, c = j & 63;
        float x = W1[(2 * k2) * 64 + c], y = W1[(2 * k2 + 1) * 64 + c];
        __nv_bfloat162 hh = __floats2bfloat162_rn(x, y);
        float2 hf = __bfloat1622float2(hh);
        __nv_bfloat162 ll = __floats2bfloat162_rn(x - hf.x, y - hf.y);
        g_w1pk[j] = make_uint2(u32bf2(hh), u32bf2(ll));
    }
}

// ---------------- bucket CSR build (one pass, no scans) ----------------------
__global__ void zero_detect_kernel(const void* ei, int n) {
    int i = blockIdx.x * blockDim.x + threadIdx.x;
    if (i < n) g_deg[i] = 0;
    if (i == 0) {
        const int* p = (const int*)ei;
        int is64 = 1;
        for (int k = 0; k < 1024; k++)
            if (p[2 * k + 1] != 0) { is64 = 0; break; }
        g_is64 = is64;
    }
}

__global__ void fill_kernel(const void* ei, int E, int ET) {
    int i = blockIdx.x * blockDim.x + threadIdx.x;
    if (i >= ET) return;
    int src, dst;
    load_edge(ei, i, E, src, dst);
    int pos = atomicAdd(&g_deg[dst], 1);
    if (pos < CAP) g_csr[(size_t)dst * CAP + pos] = src;
}

// ---------------- tensor-core GEMM (bf16x3, packed uint2 SMEM) + fused s/d --
// SMEM tiles hold {hi,lo} uint2 packs; fragment loads are LDS.64,
// conflict-free with row stride 76 (bank = 24t+2g mod 32, distinct per phase).
template <int K>
__global__ void gemm_bf16_kernel(const float* __restrict__ A,
                                 const uint2* __restrict__ wpk,
                                 const float* __restrict__ a_s,
                                 const float* __restrict__ a_d,
                                 __half* __restrict__ O, int n) {
    __shared__ __align__(16) uint2 a_pk[16][76];
    __shared__ __align__(16) uint2 b_pk[16][76];
    __shared__ float sas[64], sad[64];
    __shared__ float s_red[2][64], d_red[2][64];

    int tid  = threadIdx.x;
    int warp = tid >> 5, lane = tid & 31;
    int wm = warp >> 1, wn = warp & 1;
    int g = lane >> 2, t = lane & 3;
    int row0 = blockIdx.x * 64;

    if (tid < 64) { sas[tid] = a_s[tid]; sad[tid] = a_d[tid]; }

    float c[4][4] = {};

    for (int k0 = 0; k0 < K; k0 += 32) {
        // ---- A tile convert: 64 rows x 32 k -> packed {hi,lo}, 2 granules/thr
#pragma unroll
        for (int i = 0; i < 2; i++) {
            int idx = i * 256 + tid;               // float4 granule 0..511
            int r = idx >> 3, c4 = idx & 7;        // row, k-quad
            float4 v = make_float4(0.f, 0.f, 0.f, 0.f);
            int gr = row0 + r;
            if (gr < n) v = *(const float4*)&A[(size_t)gr * K + k0 + c4 * 4];
            __nv_bfloat162 h0 = __floats2bfloat162_rn(v.x, v.y);
            __nv_bfloat162 h1 = __floats2bfloat162_rn(v.z, v.w);
            float2 f0 = __bfloat1622float2(h0);
            float2 f1 = __bfloat1622float2(h1);
            __nv_bfloat162 l0 = __floats2bfloat162_rn(v.x - f0.x, v.y - f0.y);
            __nv_bfloat162 l1 = __floats2bfloat162_rn(v.z - f1.x, v.w - f1.y);
            a_pk[c4 * 2][r]     = make_uint2(u32bf2(h0), u32bf2(l0));
            a_pk[c4 * 2 + 1][r] = make_uint2(u32bf2(h1), u32bf2(l1));
        }
        // ---- B tile: straight copy of pre-converted packs (16 k2-rows x 64)
        {
            int r = tid >> 4, c4 = tid & 15;       // 16 x 16 granules (4 uint2)
            int gsrc = (k0 / 2 + r) * 64 + c4 * 4;
            uint4 q0 = *(const uint4*)&wpk[gsrc];
            uint4 q1 = *(const uint4*)&wpk[gsrc + 2];
            *(uint4*)&b_pk[r][c4 * 4]     = q0;
            *(uint4*)&b_pk[r][c4 * 4 + 2] = q1;
        }
        __syncthreads();

        int r0 = wm * 16 + g, r1 = r0 + 8;
#pragma unroll
        for (int kk2 = 0; kk2 < 16; kk2 += 8) {
            uint2 av0 = a_pk[kk2 + t][r0];
            uint2 av1 = a_pk[kk2 + t][r1];
            uint2 av2 = a_pk[kk2 + t + 4][r0];
            uint2 av3 = a_pk[kk2 + t + 4][r1];
            unsigned ahi[4] = { av0.x, av1.x, av2.x, av3.x };
            unsigned alo[4] = { av0.y, av1.y, av2.y, av3.y };
#pragma unroll
            for (int f = 0; f < 4; f++) {
                int col = wn * 32 + f * 8 + g;
                uint2 bv0 = b_pk[kk2 + t][col];
                uint2 bv1 = b_pk[kk2 + t + 4][col];
                unsigned bh[2] = { bv0.x, bv1.x };
                unsigned bl[2] = { bv0.y, bv1.y };
                mma16816(c[f], ahi, bh);
                mma16816(c[f], ahi, bl);
                mma16816(c[f], alo, bh);
            }
        }
        __syncthreads();
    }

    int r0 = wm * 16 + g, r1 = r0 + 8;
    int gr0 = row0 + r0, gr1 = row0 + r1;
    float s0 = 0.f, s1 = 0.f, d0 = 0.f, d1 = 0.f;
#pragma unroll
    for (int f = 0; f < 4; f++) {
        int col = wn * 32 + f * 8 + 2 * t;
        if (gr0 < n) {
            __half2 hv = __floats2half2_rn(c[f][0], c[f][1]);
            *(unsigned*)&O[(size_t)gr0 * 64 + col] = *reinterpret_cast<unsigned*>(&hv);
        }
        if (gr1 < n) {
            __half2 hv = __floats2half2_rn(c[f][2], c[f][3]);
            *(unsigned*)&O[(size_t)gr1 * 64 + col] = *reinterpret_cast<unsigned*>(&hv);
        }
        float as0 = sas[col], as1 = sas[col + 1];
        float ad0 = sad[col], ad1 = sad[col + 1];
        s0 += c[f][0] * as0 + c[f][1] * as1;
        s1 += c[f][2] * as0 + c[f][3] * as1;
        d0 += c[f][0] * ad0 + c[f][1] * ad1;
        d1 += c[f][2] * ad0 + c[f][3] * ad1;
    }
#pragma unroll
    for (int off = 1; off < 4; off <<= 1) {
        s0 += __shfl_xor_sync(0xffffffffu, s0, off);
        s1 += __shfl_xor_sync(0xffffffffu, s1, off);
        d0 += __shfl_xor_sync(0xffffffffu, d0, off);
        d1 += __shfl_xor_sync(0xffffffffu, d1, off);
    }
    if (t == 0) {
        s_red[wn][r0] = s0; s_red[wn][r1] = s1;
        d_red[wn][r0] = d0; d_red[wn][r1] = d1;
    }
    __syncthreads();
    if (tid < 64 && row0 + tid < n) {
        g_s[row0 + tid] = s_red[0][tid] + s_red[1][tid];
        g_d[row0 + tid] = d_red[0][tid] + d_red[1][tid];
    }
}

// ---------------- fused softmax + aggregation + bias + ELU ------------------
__device__ __forceinline__ float att_p(int src, float dv) {
    float ev = g_s[src] + dv;
    ev = ev > 0.f ? ev : 0.2f * ev;                // leaky_relu(0.2)
    return exp2f(ev * 1.442695041f - 6.f);          // exp(ev)*2^-6: fp16-safe
}

__global__ void agg_kernel(const __half* __restrict__ h,
                           const float* __restrict__ bias,
                           float* __restrict__ out, int n) {
    int v = (blockIdx.x * blockDim.x + threadIdx.x) >> 3;
    int l = threadIdx.x & 7;
    if (v >= n) return;
    int deg = g_deg[v];
    if (deg > CAP) deg = CAP;
    const int* row = g_csr + (size_t)v * CAP;
    const __half* hb = h + l * 8;                   // per-lane channel base
    float dv = g_d[v];
    float acc[8] = {};
    float den = 0.f;
    int e = 0;
    for (; e + 3 < deg; e += 4) {                   // 4-edge chunk
        int s0 = row[e],     s1 = row[e + 1];
        int s2 = row[e + 2], s3 = row[e + 3];
        float p0 = att_p(s0, dv);
        float p1 = att_p(s1, dv);
        float p2 = att_p(s2, dv);
        float p3 = att_p(s3, dv);
        uint4 u0 = *(const uint4*)&hb[(size_t)s0 * HID];
        uint4 u1 = *(const uint4*)&hb[(size_t)s1 * HID];
        uint4 u2 = *(const uint4*)&hb[(size_t)s2 * HID];
        uint4 u3 = *(const uint4*)&hb[(size_t)s3 * HID];
        den += (p0 + p1) + (p2 + p3);
        __half2 q0 = __float2half2_rn(p0);
        __half2 q1 = __float2half2_rn(p1);
        __half2 q2 = __float2half2_rn(p2);
        __half2 q3 = __float2half2_rn(p3);
        const __half2* h20 = reinterpret_cast<const __half2*>(&u0);
        const __half2* h21 = reinterpret_cast<const __half2*>(&u1);
        const __half2* h22 = reinterpret_cast<const __half2*>(&u2);
        const __half2* h23 = reinterpret_cast<const __half2*>(&u3);
#pragma unroll
        for (int i = 0; i < 4; i++) {
            __half2 t = __hmul2(q0, h20[i]);
            t = __hfma2(q1, h21[i], t);
            t = __hfma2(q2, h22[i], t);
            t = __hfma2(q3, h23[i], t);
            float2 f = __half22float2(t);
            acc[2 * i]     += f.x;
            acc[2 * i + 1] += f.y;
        }
    }
    for (; e < deg; e++) {                          // tail: fp32 path
        int s0 = row[e];
        float p0 = att_p(s0, dv);
        uint4 u0 = *(const uint4*)&hb[(size_t)s0 * HID];
        den += p0;
        const __half2* h20 = reinterpret_cast<const __half2*>(&u0);
#pragma unroll
        for (int i = 0; i < 4; i++) {
            float2 f = __half22float2(h20[i]);
            acc[2 * i]     += p0 * f.x;
            acc[2 * i + 1] += p0 * f.y;
        }
    }
    float inv = 1.f / (den + 1e-16f);
    float4 b0 = *(const float4*)&bias[l * 8];
    float4 b1 = *(const float4*)&bias[l * 8 + 4];
    float o[8];
#pragma unroll
    for (int i = 0; i < 8; i++) {
        float bv = (i < 4) ? ((const float*)&b0)[i] : ((const float*)&b1)[i - 4];
        float x = acc[i] * inv + bv;
        o[i] = x > 0.f ? x : expm1f(x);             // ELU
    }
    *(float4*)&out[(size_t)v * HID + l * 8]     = make_float4(o[0], o[1], o[2], o[3]);
    *(float4*)&out[(size_t)v * HID + l * 8 + 4] = make_float4(o[4], o[5], o[6], o[7]);
}

// ---------------- head: out[n,40] = h[n,64] @ Wl + bl -----------------------
__global__ void logits_kernel(const float* __restrict__ h,
                              const float* __restrict__ Wl,
                              const float* __restrict__ bl,
                              float* __restrict__ out, int n) {
    __shared__ float hs[64][65];
    __shared__ float ws[HID * NCLS];
    __shared__ float bs[NCLS];
    int tid = threadIdx.x;
    int rg = tid / 10;            // 0..15
    int cg = tid % 10;            // 0..9
    int row0 = blockIdx.x * 64;
    for (int idx = tid; idx < 64 * 16; idx += 160) {
        int r = idx >> 4, c4 = idx & 15;
        float4 v = make_float4(0.f, 0.f, 0.f, 0.f);
        int gr = row0 + r;
        if (gr < n) v = *(const float4*)&h[(size_t)gr * HID + c4 * 4];
        hs[r][c4 * 4 + 0] = v.x; hs[r][c4 * 4 + 1] = v.y;
        hs[r][c4 * 4 + 2] = v.z; hs[r][c4 * 4 + 3] = v.w;
    }
    for (int i = tid; i < HID * NCLS; i += 160) ws[i] = Wl[i];
    if (tid < NCLS) bs[tid] = bl[tid];
    __syncthreads();
    float acc[4][4];
#pragma unroll
    for (int r = 0; r < 4; r++)
#pragma unroll
        for (int c = 0; c < 4; c++) acc[r][c] = bs[cg * 4 + c];
#pragma unroll 8
    for (int k = 0; k < HID; k++) {
        float xv[4];
#pragma unroll
        for (int r = 0; r < 4; r++) xv[r] = hs[rg * 4 + r][k];
        float4 w = *(float4*)&ws[k * NCLS + cg * 4];
#pragma unroll
        for (int r = 0; r < 4; r++) {
            acc[r][0] += xv[r] * w.x; acc[r][1] += xv[r] * w.y;
            acc[r][2] += xv[r] * w.z; acc[r][3] += xv[r] * w.w;
        }
    }
#pragma unroll
    for (int r = 0; r < 4; r++) {
        int gr = row0 + rg * 4 + r;
        if (gr < n)
            *(float4*)&out[(size_t)gr * NCLS + cg * 4] =
                make_float4(acc[r][0], acc[r][1], acc[r][2], acc[r][3]);
    }
}

// ---------------- launcher --------------------------------------------------
extern "C" void kernel_launch(void* const* d_in, const int* in_sizes, int n_in,
                              void* d_out, int out_size) {
    const float* x    = (const float*)d_in[0];
    const void*  ei   = d_in[1];
    const float* W0   = (const float*)d_in[2];
    const float* a_s0 = (const float*)d_in[3];
    const float* a_d0 = (const float*)d_in[4];
    const float* b0   = (const float*)d_in[5];
    const float* W1   = (const float*)d_in[6];
    const float* a_s1 = (const float*)d_in[7];
    const float* a_d1 = (const float*)d_in[8];
    const float* b1   = (const float*)d_in[9];
    const float* Wl   = (const float*)d_in[10];
    const float* bl   = (const float*)d_in[11];
    float* out = (float*)d_out;

    int n  = in_sizes[0] / IN_DIM;   // 100000
    int E  = in_sizes[1] / 2;        // 1600000
    int ET = E + n;

    __half* hbuf;  cudaGetSymbolAddress((void**)&hbuf, g_h);
    float*  abuf;  cudaGetSymbolAddress((void**)&abuf, g_acc);
    uint2 *w0pk, *w1pk;
    cudaGetSymbolAddress((void**)&w0pk, g_w0pk);
    cudaGetSymbolAddress((void**)&w1pk, g_w1pk);

    int edgeBlocks = (ET + 255) / 256;
    int nodeBlocks = (n + 255) / 256;
    int aggBlocks  = ((size_t)n * 8 + 255) / 256;

    // Side stream + events (host objects, created once; no device memory).
    static cudaStream_t s2 = nullptr;
    static cudaEvent_t  evFork = nullptr, evJoin = nullptr;
    if (!s2) {
        cudaStreamCreateWithFlags(&s2, cudaStreamNonBlocking);
        cudaEventCreateWithFlags(&evFork, cudaEventDisableTiming);
        cudaEventCreateWithFlags(&evJoin, cudaEventDisableTiming);
    }
    cudaStream_t ms = 0;   // main (capture) stream

    // ---- W pre-conversion (main stream, before fork; GEMM0 needs it) ----
    wconv_kernel<<<((IN_DIM / 2 + HID / 2) * 64 + 255) / 256, 256, 0, ms>>>(W0, W1);

    // ---- fork: bucket-CSR build on s2, concurrent with GEMM0 on main ----
    cudaEventRecord(evFork, ms);
    cudaStreamWaitEvent(s2, evFork, 0);

    zero_detect_kernel<<<nodeBlocks, 256, 0, s2>>>(ei, n);
    fill_kernel<<<edgeBlocks, 256, 0, s2>>>(ei, E, ET);
    cudaEventRecord(evJoin, s2);

    gemm_bf16_kernel<IN_DIM><<<(n + 63) / 64, 256, 0, ms>>>(x, w0pk, a_s0, a_d0, hbuf, n);

    // ---- join: agg needs both CSR and GEMM0 ----
    cudaStreamWaitEvent(ms, evJoin, 0);
    agg_kernel<<<aggBlocks, 256, 0, ms>>>(hbuf, b0, abuf, n);

    // ---- layer 1 ----
    gemm_bf16_kernel<HID><<<(n + 63) / 64, 256, 0, ms>>>(abuf, w1pk, a_s1, a_d1, hbuf, n);
    agg_kernel<<<aggBlocks, 256, 0, ms>>>(hbuf, b1, abuf, n);

    // ---- head ----
    logits_kernel<<<(n + 63) / 64, 160, 0, ms>>>(abuf, Wl, bl, out, n);
}

// round 17
// speedup vs baseline: 1.0347x; 1.0347x over previous
#include <cuda_runtime.h>
#include <cuda_fp16.h>
#include <cuda_bf16.h>
#include <math.h>

#define N_NODES 100000
#define E_MAX   1600000
#define ET_MAX  (E_MAX + N_NODES)
#define HID     64
#define IN_DIM  128
#define NCLS    40
#define CAP     64                     // bucket capacity per node (P(overflow)~1e-19)

// ---------------- scratch (device globals; no allocation allowed) ----------
__device__ __half g_h[(size_t)N_NODES * HID];   // transformed features (fp16)
__device__ float  g_acc[(size_t)N_NODES * HID]; // layer output / next input
__device__ float  g_s[N_NODES];
__device__ float  g_d[N_NODES];
__device__ int    g_deg[N_NODES];
__device__ int    g_csr[(size_t)N_NODES * CAP]; // bucketed src lists
__device__ int    g_is64;
// pre-converted weights: packed bf16x2 of (k, k+1) pairs, k2-major [K/2][64]
__device__ unsigned g_w0hi[(IN_DIM / 2) * 64], g_w0lo[(IN_DIM / 2) * 64];
__device__ unsigned g_w1hi[(HID / 2) * 64],   g_w1lo[(HID / 2) * 64];

// ---------------- helpers ----------------------------------------------------
__device__ __forceinline__ unsigned u32bf2(__nv_bfloat162 h) {
    return *reinterpret_cast<unsigned*>(&h);
}
__device__ __forceinline__ void mma16816(float* c, const unsigned* a,
                                         const unsigned* b) {
    asm volatile(
        "mma.sync.aligned.m16n8k16.row.col.f32.bf16.bf16.f32 "
        "{%0,%1,%2,%3}, {%4,%5,%6,%7}, {%8,%9}, {%0,%1,%2,%3};"
        : "+f"(c[0]), "+f"(c[1]), "+f"(c[2]), "+f"(c[3])
        : "r"(a[0]), "r"(a[1]), "r"(a[2]), "r"(a[3]), "r"(b[0]), "r"(b[1]));
}

__device__ __forceinline__ void load_edge(const void* ei, int i, int E,
                                          int& src, int& dst) {
    if (i >= E) { int v = i - E; src = v; dst = v; return; }   // self-loop
    if (g_is64) {
        const long long* p = (const long long*)ei;
        src = (int)p[i];
        dst = (int)p[(long long)E + i];
    } else {
        const int* p = (const int*)ei;
        src = p[i];
        dst = p[E + i];
    }
}

// ---------------- weight pre-conversion (once, ~2us) -------------------------
__global__ void wconv_kernel(const float* __restrict__ W0,
                             const float* __restrict__ W1) {
    int i = blockIdx.x * blockDim.x + threadIdx.x;
    const int NW0 = (IN_DIM / 2) * 64;
    const int NW1 = (HID / 2) * 64;
    if (i < NW0) {
        int k2 = i >> 6, c = i & 63;
        float x = W0[(2 * k2) * 64 + c], y = W0[(2 * k2 + 1) * 64 + c];
        __nv_bfloat162 hh = __floats2bfloat162_rn(x, y);
        float2 hf = __bfloat1622float2(hh);
        __nv_bfloat162 ll = __floats2bfloat162_rn(x - hf.x, y - hf.y);
        g_w0hi[i] = u32bf2(hh);
        g_w0lo[i] = u32bf2(ll);
    } else if (i < NW0 + NW1) {
        int j = i - NW0;
        int k2 = j >> 6, c = j & 63;
        float x = W1[(2 * k2) * 64 + c], y = W1[(2 * k2 + 1) * 64 + c];
        __nv_bfloat162 hh = __floats2bfloat162_rn(x, y);
        float2 hf = __bfloat1622float2(hh);
        __nv_bfloat162 ll = __floats2bfloat162_rn(x - hf.x, y - hf.y);
        g_w1hi[j] = u32bf2(hh);
        g_w1lo[j] = u32bf2(ll);
    }
}

// ---------------- bucket CSR build (one pass, no scans) ----------------------
__global__ void zero_detect_kernel(const void* ei, int n) {
    int i = blockIdx.x * blockDim.x + threadIdx.x;
    if (i < n) g_deg[i] = 0;
    if (i == 0) {
        const int* p = (const int*)ei;
        int is64 = 1;
        for (int k = 0; k < 1024; k++)
            if (p[2 * k + 1] != 0) { is64 = 0; break; }
        g_is64 = is64;
    }
}

__global__ void fill_kernel(const void* ei, int E, int ET) {
    int i = blockIdx.x * blockDim.x + threadIdx.x;
    if (i >= ET) return;
    int src, dst;
    load_edge(ei, i, E, src, dst);
    int pos = atomicAdd(&g_deg[dst], 1);
    if (pos < CAP) g_csr[(size_t)dst * CAP + pos] = src;
}

// ---------------- tensor-core GEMM (bf16x3, double-buffered) + fused s/d ----
// Per chunk: prefetch next LDGs -> MMA current buffer -> convert/store next
// buffer -> ONE syncthreads. Hides LDG latency behind MMA; halves barriers.
template <int K>
__global__ void __launch_bounds__(256)
gemm_bf16_kernel(const float* __restrict__ A,
                 const unsigned* __restrict__ whi,
                 const unsigned* __restrict__ wlo,
                 const float* __restrict__ a_s,
                 const float* __restrict__ a_d,
                 __half* __restrict__ O, int n) {
    __shared__ __align__(16) unsigned a_hi[2][16][72], a_lo[2][16][72];
    __shared__ __align__(16) unsigned b_hi[2][16][72], b_lo[2][16][72];
    __shared__ float sas[64], sad[64];
    __shared__ float s_red[2][64], d_red[2][64];

    int tid  = threadIdx.x;
    int warp = tid >> 5, lane = tid & 31;
    int wm = warp >> 1, wn = warp & 1;
    int g = lane >> 2, t = lane & 3;
    int row0 = blockIdx.x * 64;

    int ar = tid >> 3, ac = tid & 7;     // A granules: rows ar, ar+32; k-quad ac
    int br = tid >> 4, bc = tid & 15;    // B granule: k2-row br, col-quad bc
    int gra0 = row0 + ar, gra1 = row0 + ar + 32;

    if (tid < 64) { sas[tid] = a_s[tid]; sad[tid] = a_d[tid]; }

    const int NCH = K / 32;
    float4 nav0, nav1;
    uint4  nbh, nbl;

    // ---- prologue: load + store chunk 0 into buffer 0 ----
    {
        nav0 = make_float4(0.f, 0.f, 0.f, 0.f);
        nav1 = nav0;
        if (gra0 < n) nav0 = *(const float4*)&A[(size_t)gra0 * K + ac * 4];
        if (gra1 < n) nav1 = *(const float4*)&A[(size_t)gra1 * K + ac * 4];
        int gsrc = br * 64 + bc * 4;
        nbh = *(const uint4*)&whi[gsrc];
        nbl = *(const uint4*)&wlo[gsrc];
    }
    {
        // A convert+store (both granules)
        float4 v = nav0;
        __nv_bfloat162 h0 = __floats2bfloat162_rn(v.x, v.y);
        __nv_bfloat162 h1 = __floats2bfloat162_rn(v.z, v.w);
        float2 f0 = __bfloat1622float2(h0), f1 = __bfloat1622float2(h1);
        a_hi[0][ac * 2][ar]     = u32bf2(h0);
        a_hi[0][ac * 2 + 1][ar] = u32bf2(h1);
        a_lo[0][ac * 2][ar]     = u32bf2(__floats2bfloat162_rn(v.x - f0.x, v.y - f0.y));
        a_lo[0][ac * 2 + 1][ar] = u32bf2(__floats2bfloat162_rn(v.z - f1.x, v.w - f1.y));
        v = nav1;
        h0 = __floats2bfloat162_rn(v.x, v.y);
        h1 = __floats2bfloat162_rn(v.z, v.w);
        f0 = __bfloat1622float2(h0); f1 = __bfloat1622float2(h1);
        a_hi[0][ac * 2][ar + 32]     = u32bf2(h0);
        a_hi[0][ac * 2 + 1][ar + 32] = u32bf2(h1);
        a_lo[0][ac * 2][ar + 32]     = u32bf2(__floats2bfloat162_rn(v.x - f0.x, v.y - f0.y));
        a_lo[0][ac * 2 + 1][ar + 32] = u32bf2(__floats2bfloat162_rn(v.z - f1.x, v.w - f1.y));
        *(uint4*)&b_hi[0][br][bc * 4] = nbh;
        *(uint4*)&b_lo[0][br][bc * 4] = nbl;
    }
    __syncthreads();

    float c[4][4] = {};
    int r0 = wm * 16 + g, r1 = r0 + 8;

    for (int ch = 0; ch < NCH; ch++) {
        int cur = ch & 1;
        // ---- prefetch next chunk ----
        if (ch + 1 < NCH) {
            int k0 = (ch + 1) * 32;
            nav0 = make_float4(0.f, 0.f, 0.f, 0.f);
            nav1 = nav0;
            if (gra0 < n) nav0 = *(const float4*)&A[(size_t)gra0 * K + k0 + ac * 4];
            if (gra1 < n) nav1 = *(const float4*)&A[(size_t)gra1 * K + k0 + ac * 4];
            int gsrc = (k0 / 2 + br) * 64 + bc * 4;
            nbh = *(const uint4*)&whi[gsrc];
            nbl = *(const uint4*)&wlo[gsrc];
        }
        // ---- MMA on current buffer ----
#pragma unroll
        for (int kk2 = 0; kk2 < 16; kk2 += 8) {
            unsigned ahi[4], alo[4];
            ahi[0] = a_hi[cur][kk2 + t][r0];     ahi[1] = a_hi[cur][kk2 + t][r1];
            ahi[2] = a_hi[cur][kk2 + t + 4][r0]; ahi[3] = a_hi[cur][kk2 + t + 4][r1];
            alo[0] = a_lo[cur][kk2 + t][r0];     alo[1] = a_lo[cur][kk2 + t][r1];
            alo[2] = a_lo[cur][kk2 + t + 4][r0]; alo[3] = a_lo[cur][kk2 + t + 4][r1];
#pragma unroll
            for (int f = 0; f < 4; f++) {
                int col = wn * 32 + f * 8 + g;
                unsigned bh[2] = { b_hi[cur][kk2 + t][col], b_hi[cur][kk2 + t + 4][col] };
                unsigned bl[2] = { b_lo[cur][kk2 + t][col], b_lo[cur][kk2 + t + 4][col] };
                mma16816(c[f], ahi, bh);
                mma16816(c[f], ahi, bl);
                mma16816(c[f], alo, bh);
            }
        }
        // ---- convert/store next chunk into other buffer ----
        if (ch + 1 < NCH) {
            int nxt = cur ^ 1;
            float4 v = nav0;
            __nv_bfloat162 h0 = __floats2bfloat162_rn(v.x, v.y);
            __nv_bfloat162 h1 = __floats2bfloat162_rn(v.z, v.w);
            float2 f0 = __bfloat1622float2(h0), f1 = __bfloat1622float2(h1);
            a_hi[nxt][ac * 2][ar]     = u32bf2(h0);
            a_hi[nxt][ac * 2 + 1][ar] = u32bf2(h1);
            a_lo[nxt][ac * 2][ar]     = u32bf2(__floats2bfloat162_rn(v.x - f0.x, v.y - f0.y));
            a_lo[nxt][ac * 2 + 1][ar] = u32bf2(__floats2bfloat162_rn(v.z - f1.x, v.w - f1.y));
            v = nav1;
            h0 = __floats2bfloat162_rn(v.x, v.y);
            h1 = __floats2bfloat162_rn(v.z, v.w);
            f0 = __bfloat1622float2(h0); f1 = __bfloat1622float2(h1);
            a_hi[nxt][ac * 2][ar + 32]     = u32bf2(h0);
            a_hi[nxt][ac * 2 + 1][ar + 32] = u32bf2(h1);
            a_lo[nxt][ac * 2][ar + 32]     = u32bf2(__floats2bfloat162_rn(v.x - f0.x, v.y - f0.y));
            a_lo[nxt][ac * 2 + 1][ar + 32] = u32bf2(__floats2bfloat162_rn(v.z - f1.x, v.w - f1.y));
            *(uint4*)&b_hi[nxt][br][bc * 4] = nbh;
            *(uint4*)&b_lo[nxt][br][bc * 4] = nbl;
            __syncthreads();
        }
    }

    // ---- epilogue: store O (fp16) + fused s/d ----
    int gr0 = row0 + r0, gr1 = row0 + r1;
    float s0 = 0.f, s1 = 0.f, d0 = 0.f, d1 = 0.f;
#pragma unroll
    for (int f = 0; f < 4; f++) {
        int col = wn * 32 + f * 8 + 2 * t;
        if (gr0 < n) {
            __half2 hv = __floats2half2_rn(c[f][0], c[f][1]);
            *(unsigned*)&O[(size_t)gr0 * 64 + col] = *reinterpret_cast<unsigned*>(&hv);
        }
        if (gr1 < n) {
            __half2 hv = __floats2half2_rn(c[f][2], c[f][3]);
            *(unsigned*)&O[(size_t)gr1 * 64 + col] = *reinterpret_cast<unsigned*>(&hv);
        }
        float as0 = sas[col], as1 = sas[col + 1];
        float ad0 = sad[col], ad1 = sad[col + 1];
        s0 += c[f][0] * as0 + c[f][1] * as1;
        s1 += c[f][2] * as0 + c[f][3] * as1;
        d0 += c[f][0] * ad0 + c[f][1] * ad1;
        d1 += c[f][2] * ad0 + c[f][3] * ad1;
    }
#pragma unroll
    for (int off = 1; off < 4; off <<= 1) {
        s0 += __shfl_xor_sync(0xffffffffu, s0, off);
        s1 += __shfl_xor_sync(0xffffffffu, s1, off);
        d0 += __shfl_xor_sync(0xffffffffu, d0, off);
        d1 += __shfl_xor_sync(0xffffffffu, d1, off);
    }
    __syncthreads();                    // all MMA reads done before s_red reuse
    if (t == 0) {
        s_red[wn][r0] = s0; s_red[wn][r1] = s1;
        d_red[wn][r0] = d0; d_red[wn][r1] = d1;
    }
    __syncthreads();
    if (tid < 64 && row0 + tid < n) {
        g_s[row0 + tid] = s_red[0][tid] + s_red[1][tid];
        g_d[row0 + tid] = d_red[0][tid] + d_red[1][tid];
    }
}

// ---------------- fused softmax + aggregation + bias + ELU ------------------
__device__ __forceinline__ float att_p(int src, float dv) {
    float ev = g_s[src] + dv;
    ev = ev > 0.f ? ev : 0.2f * ev;                // leaky_relu(0.2)
    return exp2f(ev * 1.442695041f - 6.f);          // exp(ev)*2^-6: fp16-safe
}

__global__ void agg_kernel(const __half* __restrict__ h,
                           const float* __restrict__ bias,
                           float* __restrict__ out, int n) {
    int v = (blockIdx.x * blockDim.x + threadIdx.x) >> 3;
    int l = threadIdx.x & 7;
    if (v >= n) return;
    int deg = g_deg[v];
    if (deg > CAP) deg = CAP;
    const int* row = g_csr + (size_t)v * CAP;
    const __half* hb = h + l * 8;                   // per-lane channel base
    float dv = g_d[v];
    float acc[8] = {};
    float den = 0.f;
    int e = 0;
    for (; e + 3 < deg; e += 4) {                   // 4-edge chunk
        int s0 = row[e],     s1 = row[e + 1];
        int s2 = row[e + 2], s3 = row[e + 3];
        float p0 = att_p(s0, dv);
        float p1 = att_p(s1, dv);
        float p2 = att_p(s2, dv);
        float p3 = att_p(s3, dv);
        uint4 u0 = *(const uint4*)&hb[(size_t)s0 * HID];
        uint4 u1 = *(const uint4*)&hb[(size_t)s1 * HID];
        uint4 u2 = *(const uint4*)&hb[(size_t)s2 * HID];
        uint4 u3 = *(const uint4*)&hb[(size_t)s3 * HID];
        den += (p0 + p1) + (p2 + p3);
        __half2 q0 = __float2half2_rn(p0);
        __half2 q1 = __float2half2_rn(p1);
        __half2 q2 = __float2half2_rn(p2);
        __half2 q3 = __float2half2_rn(p3);
        const __half2* h20 = reinterpret_cast<const __half2*>(&u0);
        const __half2* h21 = reinterpret_cast<const __half2*>(&u1);
        const __half2* h22 = reinterpret_cast<const __half2*>(&u2);
        const __half2* h23 = reinterpret_cast<const __half2*>(&u3);
#pragma unroll
        for (int i = 0; i < 4; i++) {
            __half2 t = __hmul2(q0, h20[i]);
            t = __hfma2(q1, h21[i], t);
            t = __hfma2(q2, h22[i], t);
            t = __hfma2(q3, h23[i], t);
            float2 f = __half22float2(t);
            acc[2 * i]     += f.x;
            acc[2 * i + 1] += f.y;
        }
    }
    for (; e < deg; e++) {                          // tail: fp32 path
        int s0 = row[e];
        float p0 = att_p(s0, dv);
        uint4 u0 = *(const uint4*)&hb[(size_t)s0 * HID];
        den += p0;
        const __half2* h20 = reinterpret_cast<const __half2*>(&u0);
#pragma unroll
        for (int i = 0; i < 4; i++) {
            float2 f = __half22float2(h20[i]);
            acc[2 * i]     += p0 * f.x;
            acc[2 * i + 1] += p0 * f.y;
        }
    }
    float inv = 1.f / (den + 1e-16f);
    float4 b0 = *(const float4*)&bias[l * 8];
    float4 b1 = *(const float4*)&bias[l * 8 + 4];
    float o[8];
#pragma unroll
    for (int i = 0; i < 8; i++) {
        float bv = (i < 4) ? ((const float*)&b0)[i] : ((const float*)&b1)[i - 4];
        float x = acc[i] * inv + bv;
        o[i] = x > 0.f ? x : expm1f(x);             // ELU
    }
    *(float4*)&out[(size_t)v * HID + l * 8]     = make_float4(o[0], o[1], o[2], o[3]);
    *(float4*)&out[(size_t)v * HID + l * 8 + 4] = make_float4(o[4], o[5], o[6], o[7]);
}

// ---------------- head: out[n,40] = h[n,64] @ Wl + bl -----------------------
__global__ void logits_kernel(const float* __restrict__ h,
                              const float* __restrict__ Wl,
                              const float* __restrict__ bl,
                              float* __restrict__ out, int n) {
    __shared__ float hs[64][65];
    __shared__ float ws[HID * NCLS];
    __shared__ float bs[NCLS];
    int tid = threadIdx.x;
    int rg = tid / 10;            // 0..15
    int cg = tid % 10;            // 0..9
    int row0 = blockIdx.x * 64;
    for (int idx = tid; idx < 64 * 16; idx += 160) {
        int r = idx >> 4, c4 = idx & 15;
        float4 v = make_float4(0.f, 0.f, 0.f, 0.f);
        int gr = row0 + r;
        if (gr < n) v = *(const float4*)&h[(size_t)gr * HID + c4 * 4];
        hs[r][c4 * 4 + 0] = v.x; hs[r][c4 * 4 + 1] = v.y;
        hs[r][c4 * 4 + 2] = v.z; hs[r][c4 * 4 + 3] = v.w;
    }
    for (int i = tid; i < HID * NCLS; i += 160) ws[i] = Wl[i];
    if (tid < NCLS) bs[tid] = bl[tid];
    __syncthreads();
    float acc[4][4];
#pragma unroll
    for (int r = 0; r < 4; r++)
#pragma unroll
        for (int c = 0; c < 4; c++) acc[r][c] = bs[cg * 4 + c];
#pragma unroll 8
    for (int k = 0; k < HID; k++) {
        float xv[4];
#pragma unroll
        for (int r = 0; r < 4; r++) xv[r] = hs[rg * 4 + r][k];
        float4 w = *(float4*)&ws[k * NCLS + cg * 4];
#pragma unroll
        for (int r = 0; r < 4; r++) {
            acc[r][0] += xv[r] * w.x; acc[r][1] += xv[r] * w.y;
            acc[r][2] += xv[r] * w.z; acc[r][3] += xv[r] * w.w;
        }
    }
#pragma unroll
    for (int r = 0; r < 4; r++) {
        int gr = row0 + rg * 4 + r;
        if (gr < n)
            *(float4*)&out[(size_t)gr * NCLS + cg * 4] =
                make_float4(acc[r][0], acc[r][1], acc[r][2], acc[r][3]);
    }
}

// ---------------- launcher --------------------------------------------------
extern "C" void kernel_launch(void* const* d_in, const int* in_sizes, int n_in,
                              void* d_out, int out_size) {
    const float* x    = (const float*)d_in[0];
    const void*  ei   = d_in[1];
    const float* W0   = (const float*)d_in[2];
    const float* a_s0 = (const float*)d_in[3];
    const float* a_d0 = (const float*)d_in[4];
    const float* b0   = (const float*)d_in[5];
    const float* W1   = (const float*)d_in[6];
    const float* a_s1 = (const float*)d_in[7];
    const float* a_d1 = (const float*)d_in[8];
    const float* b1   = (const float*)d_in[9];
    const float* Wl   = (const float*)d_in[10];
    const float* bl   = (const float*)d_in[11];
    float* out = (float*)d_out;

    int n  = in_sizes[0] / IN_DIM;   // 100000
    int E  = in_sizes[1] / 2;        // 1600000
    int ET = E + n;

    __half* hbuf;  cudaGetSymbolAddress((void**)&hbuf, g_h);
    float*  abuf;  cudaGetSymbolAddress((void**)&abuf, g_acc);
    unsigned *w0hi, *w0lo, *w1hi, *w1lo;
    cudaGetSymbolAddress((void**)&w0hi, g_w0hi);
    cudaGetSymbolAddress((void**)&w0lo, g_w0lo);
    cudaGetSymbolAddress((void**)&w1hi, g_w1hi);
    cudaGetSymbolAddress((void**)&w1lo, g_w1lo);

    int edgeBlocks = (ET + 255) / 256;
    int nodeBlocks = (n + 255) / 256;
    int aggBlocks  = ((size_t)n * 8 + 255) / 256;

    // Side stream + events (host objects, created once; no device memory).
    static cudaStream_t s2 = nullptr;
    static cudaEvent_t  evFork = nullptr, evJoin = nullptr;
    if (!s2) {
        cudaStreamCreateWithFlags(&s2, cudaStreamNonBlocking);
        cudaEventCreateWithFlags(&evFork, cudaEventDisableTiming);
        cudaEventCreateWithFlags(&evJoin, cudaEventDisableTiming);
    }
    cudaStream_t ms = 0;   // main (capture) stream

    // ---- W pre-conversion (main stream, before fork; GEMM0 needs it) ----
    wconv_kernel<<<((IN_DIM / 2 + HID / 2) * 64 + 255) / 256, 256, 0, ms>>>(W0, W1);

    // ---- fork: bucket-CSR build on s2, concurrent with GEMM0 on main ----
    cudaEventRecord(evFork, ms);
    cudaStreamWaitEvent(s2, evFork, 0);

    zero_detect_kernel<<<nodeBlocks, 256, 0, s2>>>(ei, n);
    fill_kernel<<<edgeBlocks, 256, 0, s2>>>(ei, E, ET);
    cudaEventRecord(evJoin, s2);

    gemm_bf16_kernel<IN_DIM><<<(n + 63) / 64, 256, 0, ms>>>(x, w0hi, w0lo, a_s0, a_d0, hbuf, n);

    // ---- join: agg needs both CSR and GEMM0 ----
    cudaStreamWaitEvent(ms, evJoin, 0);
    agg_kernel<<<aggBlocks, 256, 0, ms>>>(hbuf, b0, abuf, n);

    // ---- layer 1 ----
    gemm_bf16_kernel<HID><<<(n + 63) / 64, 256, 0, ms>>>(abuf, w1hi, w1lo, a_s1, a_d1, hbuf, n);
    agg_kernel<<<aggBlocks, 256, 0, ms>>>(hbuf, b1, abuf, n);

    // ---- head ----
    logits_kernel<<<(n + 63) / 64, 160, 0, ms>>>(abuf, Wl, bl, out, n);
}